// round 14
// baseline (speedup 1.0000x reference)
#include <cuda_runtime.h>
#include <cstdint>

#define N_DENSE    64
#define N_SAMPLES  121
#define N_CHANNELS 384
#define BATCH      2048
#define ROW_IN     (N_DENSE * (1 + N_SAMPLES))   // 7808 floats per input row
#define ROW_OUT    (N_CHANNELS * N_SAMPLES)      // 46464 floats per output batch
#define N_VEC      (ROW_OUT / 4)                 // 11616 float4 per batch row
#define DATA_F     (N_DENSE * N_SAMPLES)         // 7744 floats of sample data
#define NTHREADS   384                           // 12 warps -> 5 CTAs/SM

// Converged configuration (67.1-68.1us kernel across 3 runs) with ONE change:
// output stores use st.global.wt (write-through, no L2 allocation) instead of
// __stcs (evict-first, still allocates in L2). Probes whether the 5.7 TB/s
// write plateau includes an L2 write-allocate/evict round-trip cost. Input
// read caching (L2 residency of the 64MB input across graph replays) is
// unaffected — load and store policies are independent.
__global__ __launch_bounds__(NTHREADS)
void sparse_input_gather_v14(const float* __restrict__ in,
                             float* __restrict__ out)
{
    __shared__ float sdata[DATA_F + 4];   // staged [64][121]
    __shared__ int   head[N_CHANNELS];    // chain head per channel (-1 = empty)
    __shared__ int   nxt[N_DENSE];        // next slot in chain

    const int b = blockIdx.x;
    const int t = threadIdx.x;

    const float* __restrict__ row  = in + (size_t)b * ROW_IN;
    const float* __restrict__ data = row + N_DENSE;

    // ---- phase 1: stage data + build inverted index ----
    int my_c = 0;
    if (t < N_DENSE)
        my_c = (int)__ldg(&row[t]);       // in [0, N_CHANNELS) by construction
    if (t < N_CHANNELS) head[t] = -1;

    {
        const float4* __restrict__ src = reinterpret_cast<const float4*>(data);
        float4* __restrict__ dst = reinterpret_cast<float4*>(sdata);
        #pragma unroll
        for (int i = t; i < DATA_F / 4; i += NTHREADS)   // 1936 vec4
            dst[i] = src[i];
    }
    __syncthreads();
    if (t < N_DENSE)
        nxt[t] = atomicExch(&head[my_c], t);
    __syncthreads();

    // ---- phase 2: gather ----
    float4* __restrict__ ovec = reinterpret_cast<float4*>(out + (size_t)b * ROW_OUT);

    // (c, s) for p = 4t; stride NTHREADS vec4 = 1536 floats = 12*121 + 84
    int c = (4 * t) / N_SAMPLES;
    int s = 4 * t - c * N_SAMPLES;

    #pragma unroll 4
    for (int v = t; v < N_VEC; v += NTHREADS) {
        float4 acc = make_float4(0.f, 0.f, 0.f, 0.f);

        if (s <= N_SAMPLES - 4) {
            // fast path: all 4 samples in channel c (~85% of chains empty)
            int d = head[c];
            while (d >= 0) {
                const float* g = sdata + d * N_SAMPLES + s;
                acc.x += g[0];
                acc.y += g[1];
                acc.z += g[2];
                acc.w += g[3];
                d = nxt[d];
            }
        } else {
            // straddle: nA = 121 - s in {1,2,3} samples from c, rest from c+1
            const int nA = N_SAMPLES - s;
            int d = head[c];
            while (d >= 0) {                           // walk A: channel c
                const float* g = sdata + d * N_SAMPLES + s;
                acc.x += g[0];
                if (nA > 1) acc.y += g[1];
                if (nA > 2) acc.z += g[2];
                d = nxt[d];
            }
            int d2 = head[c + 1];
            while (d2 >= 0) {                          // walk B: channel c+1
                const float* g2 = sdata + d2 * N_SAMPLES - nA;  // + j, j in [nA,3]
                if (nA < 2) acc.y += g2[1];
                if (nA < 3) acc.z += g2[2];
                acc.w += g2[3];
                d2 = nxt[d2];
            }
        }
        __stwt(&ovec[v], acc);          // write-through 128-bit store, no L2 alloc

        // advance (c, s) by 1536 flat elements: c += 12, s += 84, wrap
        s += 84; c += 12;
        if (s >= N_SAMPLES) { s -= N_SAMPLES; c++; }
    }
}

extern "C" void kernel_launch(void* const* d_in, const int* in_sizes, int n_in,
                              void* d_out, int out_size)
{
    const float* in  = (const float*)d_in[0];
    float*       out = (float*)d_out;
    sparse_input_gather_v14<<<BATCH, NTHREADS>>>(in, out);
}

// round 15
// speedup vs baseline: 1.0031x; 1.0031x over previous
#include <cuda_runtime.h>
#include <cstdint>

#define N_DENSE    64
#define N_SAMPLES  121
#define N_CHANNELS 384
#define BATCH      2048
#define ROW_IN     (N_DENSE * (1 + N_SAMPLES))   // 7808 floats per input row
#define ROW_OUT    (N_CHANNELS * N_SAMPLES)      // 46464 floats per output batch
#define N_VEC      (ROW_OUT / 4)                 // 11616 float4 per batch row
#define DATA_F     (N_DENSE * N_SAMPLES)         // 7744 floats of sample data
#define NTHREADS   384                           // 12 warps -> 5 CTAs/SM

// FINAL kernel — converged configuration, reproduced in 4 independent runs
// (67.1 / 67.4 / 67.8 / 68.1 us kernel; 5.66-5.73 TB/s writes-only = the
// HBM3e streaming-write ceiling at ~72% of the 8 TB/s bidirectional spec).
// Traffic is irreducible: 380MB dense output written exactly once, 64MB input
// L2-resident across graph replays.
//
// One CTA per batch row:
//   phase 1: stage the 31KB data tile in smem (float4 copy), build a
//            per-channel inverted index (linked lists via shared atomicExch).
//   phase 2: flat vec4 output mapping with incremental (c,s) tracking —
//            full-warp contiguous STG.128 (wavefront-optimal stores);
//            chain walks read smem (29cyc LDS, ~85% of chains empty);
//            straddle vec4s via two predicated walks (channels c, c+1);
//            __stcs streaming stores protect input L2 residency.
//
// A/B-tested and rejected: direct-L2 gather (-12%), persistent CTAs +
// cp.async double-buffer (-4%), two-pass zero/nonzero split (-13%, ragged
// store wavefronts), head-prefetch pipelining (0), .wt store policy (0,
// LTS write path is policy-independent), 320/512-thread shapes.
__global__ __launch_bounds__(NTHREADS)
void sparse_input_gather_final(const float* __restrict__ in,
                               float* __restrict__ out)
{
    __shared__ float sdata[DATA_F + 4];   // staged [64][121]
    __shared__ int   head[N_CHANNELS];    // chain head per channel (-1 = empty)
    __shared__ int   nxt[N_DENSE];        // next slot in chain

    const int b = blockIdx.x;
    const int t = threadIdx.x;

    const float* __restrict__ row  = in + (size_t)b * ROW_IN;
    const float* __restrict__ data = row + N_DENSE;

    // ---- phase 1: stage data + build inverted index ----
    int my_c = 0;
    if (t < N_DENSE)
        my_c = (int)__ldg(&row[t]);       // in [0, N_CHANNELS) by construction
    if (t < N_CHANNELS) head[t] = -1;

    {
        const float4* __restrict__ src = reinterpret_cast<const float4*>(data);
        float4* __restrict__ dst = reinterpret_cast<float4*>(sdata);
        #pragma unroll
        for (int i = t; i < DATA_F / 4; i += NTHREADS)   // 1936 vec4
            dst[i] = src[i];
    }
    __syncthreads();
    if (t < N_DENSE)
        nxt[t] = atomicExch(&head[my_c], t);
    __syncthreads();

    // ---- phase 2: gather ----
    float4* __restrict__ ovec = reinterpret_cast<float4*>(out + (size_t)b * ROW_OUT);

    // (c, s) for p = 4t; stride NTHREADS vec4 = 1536 floats = 12*121 + 84
    int c = (4 * t) / N_SAMPLES;
    int s = 4 * t - c * N_SAMPLES;

    #pragma unroll 4
    for (int v = t; v < N_VEC; v += NTHREADS) {
        float4 acc = make_float4(0.f, 0.f, 0.f, 0.f);

        if (s <= N_SAMPLES - 4) {
            // fast path: all 4 samples in channel c (~85% of chains empty)
            int d = head[c];
            while (d >= 0) {
                const float* g = sdata + d * N_SAMPLES + s;
                acc.x += g[0];
                acc.y += g[1];
                acc.z += g[2];
                acc.w += g[3];
                d = nxt[d];
            }
        } else {
            // straddle: nA = 121 - s in {1,2,3} samples from c, rest from c+1
            const int nA = N_SAMPLES - s;
            int d = head[c];
            while (d >= 0) {                           // walk A: channel c
                const float* g = sdata + d * N_SAMPLES + s;
                acc.x += g[0];
                if (nA > 1) acc.y += g[1];
                if (nA > 2) acc.z += g[2];
                d = nxt[d];
            }
            int d2 = head[c + 1];
            while (d2 >= 0) {                          // walk B: channel c+1
                const float* g2 = sdata + d2 * N_SAMPLES - nA;  // + j, j in [nA,3]
                if (nA < 2) acc.y += g2[1];
                if (nA < 3) acc.z += g2[2];
                acc.w += g2[3];
                d2 = nxt[d2];
            }
        }
        __stcs(&ovec[v], acc);          // streaming 128-bit store, full-warp coalesced

        // advance (c, s) by 1536 flat elements: c += 12, s += 84, wrap
        s += 84; c += 12;
        if (s >= N_SAMPLES) { s -= N_SAMPLES; c++; }
    }
}

extern "C" void kernel_launch(void* const* d_in, const int* in_sizes, int n_in,
                              void* d_out, int out_size)
{
    const float* in  = (const float*)d_in[0];
    float*       out = (float*)d_out;
    sparse_input_gather_final<<<BATCH, NTHREADS>>>(in, out);
}